// round 15
// baseline (speedup 1.0000x reference)
#include <cuda_runtime.h>
#include <cuda_fp16.h>
#include <math.h>

// Problem constants (fixed by the dataset generator)
#define NATOMS 8192
#define NEDGE  262144
#define KNB    32
#define HD     128
#define NFH    128
#define NGAUSS 50
#define NLAY   6
#define NGRAPH 32
#define NPERG  256
#define CUTR   10.0f
#define LOG2F_ 0.69314718055994530942f
#define PI_F   3.14159265358979323846f

// filter lookup table
#define MTAB   2048
#define DMAXT  8.661f
#define DELTA  (DMAXT / (float)(MTAB - 1))

typedef unsigned long long u64;

// packed f32x2 fma
#define FMA2(d, a, b, c) \
    asm("fma.rn.f32x2 %0, %1, %2, %3;" : "=l"(d) : "l"(a), "l"(b), "l"(c))
#define PACK2(d, x) \
    do { unsigned _u = __float_as_uint(x); \
         asm("mov.b64 %0, {%1, %1};" : "=l"(d) : "r"(_u)); } while (0)
#define UNPACK2(lo, hi, p) \
    do { unsigned _a, _b; \
         asm("mov.b64 {%0, %1}, %2;" : "=r"(_a), "=r"(_b) : "l"(p)); \
         lo = __uint_as_float(_a); hi = __uint_as_float(_b); } while (0)

// ---------------- device scratch ----------------
__device__ __half g_WtabH[NLAY * MTAB * HD];  // fp16 filter tables, 3.1 MB
__device__ int    g_koff[NEDGE];              // byte offset of table row k
__device__ float  g_al[NEDGE];
__device__ float  g_h[NATOMS * HD];
__device__ __half g_Xh[NATOMS * NFH];         // fp16 X (gather's only input)
__device__ float  g_agg[NATOMS * NFH];
__device__ float  g_S;

__device__ __forceinline__ float sspf(float x) {
    float e = __expf(-fabsf(x));
    return fmaxf(x, 0.0f) + __logf(1.0f + e) - LOG2F_;
}

__device__ __forceinline__ uint4 pack8h(const float* a) {
    __half2 h0 = __floats2half2_rn(a[0], a[1]);
    __half2 h1 = __floats2half2_rn(a[2], a[3]);
    __half2 h2 = __floats2half2_rn(a[4], a[5]);
    __half2 h3 = __floats2half2_rn(a[6], a[7]);
    uint4 pk;
    pk.x = *(unsigned*)&h0; pk.y = *(unsigned*)&h1;
    pk.z = *(unsigned*)&h2; pk.w = *(unsigned*)&h3;
    return pk;
}

// ---------------- edge precompute + output zero (fused) ----------------
__global__ void __launch_bounds__(256) edge_pre_kernel(const float* __restrict__ pos,
                                                       const int* __restrict__ ei,
                                                       float* __restrict__ out, int out_n) {
    int gid = blockIdx.x * blockDim.x + threadIdx.x;
    for (int e = gid; e < NEDGE; e += gridDim.x * blockDim.x) {
        int s = ei[e], t = ei[NEDGE + e];
        float dx = pos[3 * s + 0] - pos[3 * t + 0];
        float dy = pos[3 * s + 1] - pos[3 * t + 1];
        float dz = pos[3 * s + 2] - pos[3 * t + 2];
        float d = sqrtf(dx * dx + dy * dy + dz * dz);
        float tt = d * ((float)(MTAB - 1) / DMAXT);
        int k = (int)tt;
        if (k > MTAB - 2) k = MTAB - 2;
        g_koff[e] = k * (HD * 2);            // byte offset
        g_al[e] = tt - (float)k;
    }
    for (int i = gid; i < out_n; i += gridDim.x * blockDim.x)
        out[i] = 0.0f;
}

// ---------------- filter table build (proven stage-A/B SIMT core, fp16 out) ----------
__global__ void __launch_bounds__(256, 1) table_kernel(
    const float* __restrict__ w1a, const float* __restrict__ b1a,
    const float* __restrict__ w2a, const float* __restrict__ b2a)
{
    extern __shared__ float sm[];
    float* s_w1 = sm;                        // [50][128]
    float* s_b1 = s_w1 + NGAUSS * NFH;
    float* s_b2 = s_b1 + NFH;
    float* s_w2 = s_b2 + NFH;                // [128][128]
    float* s_ea = s_w2 + NFH * NFH;          // [50][128]
    float* s_tT = s_ea + NGAUSS * 128;       // [128][128] swizzled

    const int l  = blockIdx.x >> 4;          // MTAB/128 = 16 blocks per layer
    const int m0 = (blockIdx.x & 15) * 128;
    const float* w1 = w1a + l * NGAUSS * NFH;
    const float* b1 = b1a + l * NFH;
    const float* w2 = w2a + l * NFH * NFH;
    const float* b2 = b2a + l * NFH;

    const int tid = threadIdx.x;
    for (int i = tid; i < NGAUSS * NFH; i += 256) s_w1[i] = w1[i];
    for (int i = tid; i < NFH * NFH;   i += 256) s_w2[i] = w2[i];
    if (tid < NFH) { s_b1[tid] = b1[tid]; s_b2[tid] = b2[tid]; }

    const float step  = CUTR / (float)(NGAUSS - 1);
    const float coeff = -0.5f / (step * step);
    for (int i = tid; i < NGAUSS * 128; i += 256) {
        int j = i >> 7, r = i & 127;
        float d = (float)(m0 + r) * DELTA;
        float u = d - (float)j * step;
        s_ea[j * 128 + r] = __expf(coeff * u * u);
    }
    __syncthreads();

    const int f8 = tid & 15, eg = tid >> 4;
    const int f0 = f8 * 8,   e0 = eg * 8;
    const int xf = (f8 & 7) << 2;

    u64 acc2[8][4];
    {
        const ulonglong2* bp = (const ulonglong2*)&s_b1[f0];
        ulonglong2 bA = bp[0], bB = bp[1];
#pragma unroll
        for (int ee = 0; ee < 8; ee++) {
            acc2[ee][0] = bA.x; acc2[ee][1] = bA.y;
            acc2[ee][2] = bB.x; acc2[ee][3] = bB.y;
        }
    }
    for (int j = 0; j < NGAUSS; j++) {
        const ulonglong2* wp = (const ulonglong2*)&s_w1[j * NFH + f0];
        ulonglong2 wA = wp[0], wB = wp[1];
        float4 ea0 = *(const float4*)&s_ea[j * 128 + e0];
        float4 ea1 = *(const float4*)&s_ea[j * 128 + e0 + 4];
        float ev[8] = {ea0.x, ea0.y, ea0.z, ea0.w, ea1.x, ea1.y, ea1.z, ea1.w};
#pragma unroll
        for (int ee = 0; ee < 8; ee++) {
            u64 evp; PACK2(evp, ev[ee]);
            FMA2(acc2[ee][0], evp, wA.x, acc2[ee][0]);
            FMA2(acc2[ee][1], evp, wA.y, acc2[ee][1]);
            FMA2(acc2[ee][2], evp, wB.x, acc2[ee][2]);
            FMA2(acc2[ee][3], evp, wB.y, acc2[ee][3]);
        }
    }
    {
        float a[8][8];
#pragma unroll
        for (int ee = 0; ee < 8; ee++)
#pragma unroll
            for (int fp = 0; fp < 4; fp++)
                UNPACK2(a[ee][2 * fp], a[ee][2 * fp + 1], acc2[ee][fp]);
#pragma unroll
        for (int ff = 0; ff < 8; ff++) {
            float4 v0 = make_float4(sspf(a[0][ff]), sspf(a[1][ff]),
                                    sspf(a[2][ff]), sspf(a[3][ff]));
            float4 v1 = make_float4(sspf(a[4][ff]), sspf(a[5][ff]),
                                    sspf(a[6][ff]), sspf(a[7][ff]));
            *(float4*)&s_tT[(f0 + ff) * NFH + (e0 ^ xf)]       = v0;
            *(float4*)&s_tT[(f0 + ff) * NFH + ((e0 + 4) ^ xf)] = v1;
        }
    }
    __syncthreads();

    {
        const ulonglong2* bp = (const ulonglong2*)&s_b2[f0];
        ulonglong2 bA = bp[0], bB = bp[1];
#pragma unroll
        for (int ee = 0; ee < 8; ee++) {
            acc2[ee][0] = bA.x; acc2[ee][1] = bA.y;
            acc2[ee][2] = bB.x; acc2[ee][3] = bB.y;
        }
    }
    for (int j = 0; j < NFH; j++) {
        const ulonglong2* wp = (const ulonglong2*)&s_w2[j * NFH + f0];
        ulonglong2 wA = wp[0], wB = wp[1];
        const int xj = ((j >> 3) & 7) << 2;
        float4 t0 = *(const float4*)&s_tT[j * NFH + (e0 ^ xj)];
        float4 t1 = *(const float4*)&s_tT[j * NFH + ((e0 + 4) ^ xj)];
        float tv[8] = {t0.x, t0.y, t0.z, t0.w, t1.x, t1.y, t1.z, t1.w};
#pragma unroll
        for (int ee = 0; ee < 8; ee++) {
            u64 tp; PACK2(tp, tv[ee]);
            FMA2(acc2[ee][0], tp, wA.x, acc2[ee][0]);
            FMA2(acc2[ee][1], tp, wA.y, acc2[ee][1]);
            FMA2(acc2[ee][2], tp, wB.x, acc2[ee][2]);
            FMA2(acc2[ee][3], tp, wB.y, acc2[ee][3]);
        }
    }

#pragma unroll
    for (int ee = 0; ee < 8; ee++) {
        float a[8];
#pragma unroll
        for (int fp = 0; fp < 4; fp++) UNPACK2(a[2 * fp], a[2 * fp + 1], acc2[ee][fp]);
        int m = m0 + e0 + ee;
        float d = (float)m * DELTA;
        float Cr = 0.5f * (cosf(d * (PI_F / CUTR)) + 1.0f);
        float b[8];
#pragma unroll
        for (int q = 0; q < 8; q++) b[q] = a[q] * Cr;
        *(uint4*)&g_WtabH[((size_t)l * MTAB + m) * HD + f0] = pack8h(b);
    }
}

// ---------------- gather: warp per atom, half2 lerp+mul, fp32 accumulate ----------
__global__ void __launch_bounds__(256) gather_kernel(const int* __restrict__ ei, int layer)
{
    const int warp = threadIdx.x >> 5, lane = threadIdx.x & 31;
    const int atom = blockIdx.x * 8 + warp;
    const int eb = atom * KNB;
    const char* tab = (const char*)&g_WtabH[(size_t)layer * MTAB * HD] + lane * 8;

    int   ko_r  = g_koff[eb + lane];
    float al_r  = g_al[eb + lane];
    int   src_r = ei[eb + lane];

    float4 acc = make_float4(0.0f, 0.0f, 0.0f, 0.0f);
#pragma unroll 4
    for (int e = 0; e < KNB; e++) {
        int   ko = __shfl_sync(0xffffffffu, ko_r,  e);
        float al = __shfl_sync(0xffffffffu, al_r,  e);
        int   s  = __shfl_sync(0xffffffffu, src_r, e);
        const char* base = tab + ko;
        uint2 u0 = *(const uint2*)base;
        uint2 u1 = *(const uint2*)(base + HD * 2);
        uint2 ux = *(const uint2*)&g_Xh[s * HD + lane * 4];
        __half2 al2 = __float2half2_rn(al);
        __half2 a0 = *(__half2*)&u0.x, a1 = *(__half2*)&u0.y;
        __half2 b0 = *(__half2*)&u1.x, b1 = *(__half2*)&u1.y;
        __half2 x0 = *(__half2*)&ux.x, x1 = *(__half2*)&ux.y;
        __half2 w0 = __hfma2(al2, __hsub2(b0, a0), a0);
        __half2 w1 = __hfma2(al2, __hsub2(b1, a1), a1);
        float2 p0 = __half22float2(__hmul2(x0, w0));
        float2 p1 = __half22float2(__hmul2(x1, w1));
        acc.x += p0.x; acc.y += p0.y; acc.z += p1.x; acc.w += p1.y;
    }
    *(float4*)&g_agg[atom * HD + lane * 4] = acc;
}

// ------- node GEMM: Xh = (emb[z]) @ cf1 (fp16 out) + g_h; block 128 does FiLM bias -----
__global__ void __launch_bounds__(256, 1) gemm0_kernel(
    const float* __restrict__ W, const int* __restrict__ z, const float* __restrict__ emb,
    const int* __restrict__ dom_ids, const float* __restrict__ dom_emb,
    const float* __restrict__ fw1, const float* __restrict__ fb1,
    const float* __restrict__ fw2, const float* __restrict__ fb2,
    const float* __restrict__ bw,  const float* __restrict__ bb)
{
    extern __shared__ float smem_dyn[];
    const int tid = threadIdx.x;

    if (blockIdx.x == 128) {
        // ---- FiLM bias, algebraically collapsed ----
        float* s_v  = smem_dyn;              // [128]
        float* s_u  = s_v + 128;             // [128]
        float* s_de = s_u + 128;             // [32*64]
        float* s_rd = s_de + NGRAPH * 64;    // [8]
        if (tid < 128) {
            float s = 0.0f;
            const float4* r = (const float4*)&bw[tid * 128];
#pragma unroll 8
            for (int h = 0; h < 32; h++) { float4 v = r[h]; s += v.x + v.y + v.z + v.w; }
            s_v[tid] = s;
        }
        for (int i = tid; i < NGRAPH * 64; i += 256) {
            int g = i >> 6, k = i & 63;
            s_de[i] = dom_emb[dom_ids[g] * 64 + k];
        }
        __syncthreads();
        if (tid < 128) {
            float s = 0.0f;
            const float4* r = (const float4*)&fw2[tid * 128];
            const float4* v4 = (const float4*)s_v;
#pragma unroll 8
            for (int k = 0; k < 32; k++) {
                float4 w = r[k], v = v4[k];
                s += w.x * v.x + w.y * v.y + w.z * v.z + w.w * v.w;
            }
            s_u[tid] = s;
        }
        __syncthreads();
        float sl = 0.0f;
        if (tid < 128) sl += (float)NGRAPH * (fb2[tid] * s_v[tid] + bb[tid]);
        for (int idx = tid; idx < NGRAPH * 128; idx += 256) {
            int g = idx >> 7, j = idx & 127;
            float a = fb1[j];
#pragma unroll 4
            for (int i = 0; i < 64; i++) a += s_de[g * 64 + i] * fw1[i * 128 + j];
            sl += fmaxf(a, 0.0f) * s_u[j];
        }
        for (int o = 16; o; o >>= 1) sl += __shfl_xor_sync(0xffffffffu, sl, o);
        if ((tid & 31) == 0) s_rd[tid >> 5] = sl;
        __syncthreads();
        if (tid == 0) {
            float v = 0.0f;
            for (int w = 0; w < 8; w++) v += s_rd[w];
            g_S = v;
        }
        return;
    }

    float* s_w = smem_dyn;
    float* s_x = s_w + NFH * NFH;
    for (int i = tid; i < NFH * NFH; i += 256) s_w[i] = W[i];
    __syncthreads();

    const int f8 = tid & 15, aq = tid >> 4;
    const int f0 = f8 * 8,   a0 = aq * 4;
    const int abase = blockIdx.x * 64;

    for (int i = tid; i < 64 * NFH; i += 256) {
        int a = i >> 7, f = i & 127;
        float v = emb[z[abase + a] * HD + f];
        s_x[i] = v;
        g_h[abase * NFH + i] = v;
    }
    __syncthreads();

    u64 acc2[4][4];
#pragma unroll
    for (int aa = 0; aa < 4; aa++)
#pragma unroll
        for (int k = 0; k < 4; k++) acc2[aa][k] = 0ull;
    for (int j = 0; j < NFH; j++) {
        const ulonglong2* wp = (const ulonglong2*)&s_w[j * NFH + f0];
        ulonglong2 wA = wp[0], wB = wp[1];
#pragma unroll
        for (int aa = 0; aa < 4; aa++) {
            float xv = s_x[(a0 + aa) * NFH + j];
            u64 xp; PACK2(xp, xv);
            FMA2(acc2[aa][0], xp, wA.x, acc2[aa][0]);
            FMA2(acc2[aa][1], xp, wA.y, acc2[aa][1]);
            FMA2(acc2[aa][2], xp, wB.x, acc2[aa][2]);
            FMA2(acc2[aa][3], xp, wB.y, acc2[aa][3]);
        }
    }
#pragma unroll
    for (int aa = 0; aa < 4; aa++) {
        float a[8];
#pragma unroll
        for (int fp = 0; fp < 4; fp++) UNPACK2(a[2 * fp], a[2 * fp + 1], acc2[aa][fp]);
        *(uint4*)&g_Xh[(abase + a0 + aa) * NFH + f0] = pack8h(a);
    }
}

// ---- fused node chain (64-atom tiles): P=ssp(agg@cf2+b2); h+=P@intw+bi; Xh=h@cf1n ----
template <int HAS_NEXT>
__global__ void __launch_bounds__(256, 1) node_fused_kernel(
    const float* __restrict__ cf2w, const float* __restrict__ cf2b,
    const float* __restrict__ intw, const float* __restrict__ intb,
    const float* __restrict__ cf1n)
{
    extern __shared__ float sm[];
    float* s_w2 = sm;                                  // [128][128]
    float* s_wi = s_w2 + NFH * NFH;                    // [128][128]
    float* s_wn = s_wi + NFH * NFH;                    // [128][128] if HAS_NEXT
    float* s_x  = s_wn + (HAS_NEXT ? NFH * NFH : 0);   // [64][128]
    float* s_b2 = s_x + 64 * NFH;                      // [128]
    float* s_bi = s_b2 + NFH;                          // [128]

    const int tid = threadIdx.x;
    for (int i = tid; i < NFH * NFH; i += 256) s_w2[i] = cf2w[i];
    for (int i = tid; i < NFH * NFH; i += 256) s_wi[i] = intw[i];
    if (HAS_NEXT)
        for (int i = tid; i < NFH * NFH; i += 256) s_wn[i] = cf1n[i];
    if (tid < NFH) { s_b2[tid] = cf2b[tid]; s_bi[tid] = intb[tid]; }

    const int f8 = tid & 15, aq = tid >> 4;
    const int f0 = f8 * 8,   a0 = aq * 4;
    const int abase = blockIdx.x * 64;                 // grid = 128

    for (int i = tid; i < 64 * NFH; i += 256)
        s_x[i] = g_agg[abase * NFH + i];
    __syncthreads();

    u64 acc2[4][4];
    // ---- GEMM1: P = ssp(agg @ cf2 + b2) ----
    {
        const ulonglong2* bp = (const ulonglong2*)&s_b2[f0];
        ulonglong2 bA = bp[0], bB = bp[1];
#pragma unroll
        for (int aa = 0; aa < 4; aa++) {
            acc2[aa][0] = bA.x; acc2[aa][1] = bA.y;
            acc2[aa][2] = bB.x; acc2[aa][3] = bB.y;
        }
    }
    for (int j = 0; j < NFH; j++) {
        const ulonglong2* wp = (const ulonglong2*)&s_w2[j * NFH + f0];
        ulonglong2 wA = wp[0], wB = wp[1];
#pragma unroll
        for (int aa = 0; aa < 4; aa++) {
            float xv = s_x[(a0 + aa) * NFH + j];
            u64 xp; PACK2(xp, xv);
            FMA2(acc2[aa][0], xp, wA.x, acc2[aa][0]);
            FMA2(acc2[aa][1], xp, wA.y, acc2[aa][1]);
            FMA2(acc2[aa][2], xp, wB.x, acc2[aa][2]);
            FMA2(acc2[aa][3], xp, wB.y, acc2[aa][3]);
        }
    }
    float P[4][8];
#pragma unroll
    for (int aa = 0; aa < 4; aa++) {
        float a[8];
#pragma unroll
        for (int fp = 0; fp < 4; fp++) UNPACK2(a[2 * fp], a[2 * fp + 1], acc2[aa][fp]);
#pragma unroll
        for (int q = 0; q < 8; q++) P[aa][q] = sspf(a[q]);
    }
    __syncthreads();
#pragma unroll
    for (int aa = 0; aa < 4; aa++) {
        *(float4*)&s_x[(a0 + aa) * NFH + f0]     = make_float4(P[aa][0], P[aa][1], P[aa][2], P[aa][3]);
        *(float4*)&s_x[(a0 + aa) * NFH + f0 + 4] = make_float4(P[aa][4], P[aa][5], P[aa][6], P[aa][7]);
    }
    __syncthreads();

    // ---- GEMM2: hnew = h + P @ intw + bi ----
    {
        const ulonglong2* bp = (const ulonglong2*)&s_bi[f0];
        ulonglong2 bA = bp[0], bB = bp[1];
#pragma unroll
        for (int aa = 0; aa < 4; aa++) {
            acc2[aa][0] = bA.x; acc2[aa][1] = bA.y;
            acc2[aa][2] = bB.x; acc2[aa][3] = bB.y;
        }
    }
    for (int j = 0; j < NFH; j++) {
        const ulonglong2* wp = (const ulonglong2*)&s_wi[j * NFH + f0];
        ulonglong2 wA = wp[0], wB = wp[1];
#pragma unroll
        for (int aa = 0; aa < 4; aa++) {
            float xv = s_x[(a0 + aa) * NFH + j];
            u64 xp; PACK2(xp, xv);
            FMA2(acc2[aa][0], xp, wA.x, acc2[aa][0]);
            FMA2(acc2[aa][1], xp, wA.y, acc2[aa][1]);
            FMA2(acc2[aa][2], xp, wB.x, acc2[aa][2]);
            FMA2(acc2[aa][3], xp, wB.y, acc2[aa][3]);
        }
    }
    float hnew[4][8];
#pragma unroll
    for (int aa = 0; aa < 4; aa++) {
        float a[8];
#pragma unroll
        for (int fp = 0; fp < 4; fp++) UNPACK2(a[2 * fp], a[2 * fp + 1], acc2[aa][fp]);
        int row = (abase + a0 + aa) * NFH + f0;
        float4 y0 = *(const float4*)&g_h[row];
        float4 y1 = *(const float4*)&g_h[row + 4];
        hnew[aa][0] = y0.x + a[0]; hnew[aa][1] = y0.y + a[1];
        hnew[aa][2] = y0.z + a[2]; hnew[aa][3] = y0.w + a[3];
        hnew[aa][4] = y1.x + a[4]; hnew[aa][5] = y1.y + a[5];
        hnew[aa][6] = y1.z + a[6]; hnew[aa][7] = y1.w + a[7];
        *(float4*)&g_h[row]     = make_float4(hnew[aa][0], hnew[aa][1], hnew[aa][2], hnew[aa][3]);
        *(float4*)&g_h[row + 4] = make_float4(hnew[aa][4], hnew[aa][5], hnew[aa][6], hnew[aa][7]);
    }

    if (HAS_NEXT) {
        __syncthreads();
#pragma unroll
        for (int aa = 0; aa < 4; aa++) {
            *(float4*)&s_x[(a0 + aa) * NFH + f0]     =
                make_float4(hnew[aa][0], hnew[aa][1], hnew[aa][2], hnew[aa][3]);
            *(float4*)&s_x[(a0 + aa) * NFH + f0 + 4] =
                make_float4(hnew[aa][4], hnew[aa][5], hnew[aa][6], hnew[aa][7]);
        }
        __syncthreads();

        // ---- GEMM3: Xh = hnew @ cf1next (fp16 out) ----
#pragma unroll
        for (int aa = 0; aa < 4; aa++)
#pragma unroll
            for (int k = 0; k < 4; k++) acc2[aa][k] = 0ull;
        for (int j = 0; j < NFH; j++) {
            const ulonglong2* wp = (const ulonglong2*)&s_wn[j * NFH + f0];
            ulonglong2 wA = wp[0], wB = wp[1];
#pragma unroll
            for (int aa = 0; aa < 4; aa++) {
                float xv = s_x[(a0 + aa) * NFH + j];
                u64 xp; PACK2(xp, xv);
                FMA2(acc2[aa][0], xp, wA.x, acc2[aa][0]);
                FMA2(acc2[aa][1], xp, wA.y, acc2[aa][1]);
                FMA2(acc2[aa][2], xp, wB.x, acc2[aa][2]);
                FMA2(acc2[aa][3], xp, wB.y, acc2[aa][3]);
            }
        }
#pragma unroll
        for (int aa = 0; aa < 4; aa++) {
            float a[8];
#pragma unroll
            for (int fp = 0; fp < 4; fp++) UNPACK2(a[2 * fp], a[2 * fp + 1], acc2[aa][fp]);
            *(uint4*)&g_Xh[(abase + a0 + aa) * NFH + f0] = pack8h(a);
        }
    }
}

// ---------------- output head ----------------
__global__ void __launch_bounds__(256) energy_kernel(
    const float* __restrict__ w1, const float* __restrict__ b1,
    const float* __restrict__ w2, const float* __restrict__ b2,
    float* __restrict__ out)
{
    __shared__ float s_w1[HD * 64];
    __shared__ float s_w2[64];
    __shared__ float s_red[8];
    int tid = threadIdx.x;
    for (int i = tid; i < HD * 64; i += 256) s_w1[i] = w1[i];
    if (tid < 64) s_w2[tid] = w2[tid];
    __syncthreads();

    int atom = blockIdx.x * NPERG + tid;
    float e = b2[0];
#pragma unroll
    for (int half = 0; half < 2; half++) {
        float u[32];
#pragma unroll
        for (int f = 0; f < 32; f++) u[f] = b1[half * 32 + f];
        for (int j = 0; j < HD; j++) {
            float hv = g_h[atom * HD + j];
#pragma unroll
            for (int f = 0; f < 32; f++) u[f] += hv * s_w1[j * 64 + half * 32 + f];
        }
#pragma unroll
        for (int f = 0; f < 32; f++) e += sspf(u[f]) * s_w2[half * 32 + f];
    }

    for (int o = 16; o; o >>= 1) e += __shfl_xor_sync(0xffffffffu, e, o);
    if ((tid & 31) == 0) s_red[tid >> 5] = e;
    __syncthreads();
    if (tid == 0) {
        float tot = 0.0f;
        for (int w = 0; w < 8; w++) tot += s_red[w];
        out[blockIdx.x] = (float)NGRAPH * tot + g_S;
    }
}

// ---------------- launch ----------------
extern "C" void kernel_launch(void* const* d_in, const int* in_sizes, int n_in,
                              void* d_out, int out_size)
{
    const float* pos    = (const float*)d_in[0];
    const int*   z      = (const int*)  d_in[1];
    const int*   ei     = (const int*)  d_in[3];
    const int*   dom    = (const int*)  d_in[4];
    const float* emb    = (const float*)d_in[5];
    const float* mlp_w1 = (const float*)d_in[6];
    const float* mlp_b1 = (const float*)d_in[7];
    const float* mlp_w2 = (const float*)d_in[8];
    const float* mlp_b2 = (const float*)d_in[9];
    const float* cf1    = (const float*)d_in[10];
    const float* cf2    = (const float*)d_in[11];
    const float* cf2b   = (const float*)d_in[12];
    const float* intw   = (const float*)d_in[13];
    const float* intb   = (const float*)d_in[14];
    const float* ow1    = (const float*)d_in[15];
    const float* ob1    = (const float*)d_in[16];
    const float* ow2    = (const float*)d_in[17];
    const float* ob2    = (const float*)d_in[18];
    const float* dome   = (const float*)d_in[19];
    const float* fw1    = (const float*)d_in[20];
    const float* fb1    = (const float*)d_in[21];
    const float* fw2    = (const float*)d_in[22];
    const float* fb2    = (const float*)d_in[23];
    const float* bw     = (const float*)d_in[26];
    const float* bb     = (const float*)d_in[27];
    float* out = (float*)d_out;

    const int TAB_SMEM  = (NGAUSS * NFH + NFH + NFH + NFH * NFH +
                           NGAUSS * 128 + 128 * NFH) * (int)sizeof(float);
    const int GEMM0_SMEM = (NFH * NFH + 64 * NFH) * (int)sizeof(float);  // bias block needs < this
    const int NF1_SMEM  = (3 * NFH * NFH + 64 * NFH + 2 * NFH) * (int)sizeof(float);
    const int NF0_SMEM  = (2 * NFH * NFH + 64 * NFH + 2 * NFH) * (int)sizeof(float);

    cudaFuncSetAttribute(table_kernel,  cudaFuncAttributeMaxDynamicSharedMemorySize, TAB_SMEM);
    cudaFuncSetAttribute(gemm0_kernel,  cudaFuncAttributeMaxDynamicSharedMemorySize, GEMM0_SMEM);
    cudaFuncSetAttribute(node_fused_kernel<1>, cudaFuncAttributeMaxDynamicSharedMemorySize, NF1_SMEM);
    cudaFuncSetAttribute(node_fused_kernel<0>, cudaFuncAttributeMaxDynamicSharedMemorySize, NF0_SMEM);

    edge_pre_kernel<<<1024, 256>>>(pos, ei, out, out_size);
    table_kernel<<<NLAY * (MTAB / 128), 256, TAB_SMEM>>>(mlp_w1, mlp_b1, mlp_w2, mlp_b2);
    gemm0_kernel<<<129, 256, GEMM0_SMEM>>>(cf1, z, emb,
                                           dom, dome, fw1, fb1, fw2, fb2, bw, bb);
    gather_kernel<<<NATOMS / 8, 256>>>(ei, 0);      // layer 0 (ncu-captured slot)

    node_fused_kernel<1><<<NATOMS / 64, 256, NF1_SMEM>>>(cf2, cf2b, intw, intb,
                                                         cf1 + 1 * HD * NFH);

    for (int l = 1; l < NLAY; l++) {
        gather_kernel<<<NATOMS / 8, 256>>>(ei, l);
        if (l + 1 < NLAY)
            node_fused_kernel<1><<<NATOMS / 64, 256, NF1_SMEM>>>(
                cf2 + l * NFH * HD, cf2b + l * HD,
                intw + l * HD * HD, intb + l * HD,
                cf1 + (l + 1) * HD * NFH);
        else
            node_fused_kernel<0><<<NATOMS / 64, 256, NF0_SMEM>>>(
                cf2 + l * NFH * HD, cf2b + l * HD,
                intw + l * HD * HD, intb + l * HD,
                nullptr);
    }

    energy_kernel<<<NGRAPH, 256>>>(ow1, ob1, ow2, ob2, out);
}

// round 16
// speedup vs baseline: 1.4724x; 1.4724x over previous
#include <cuda_runtime.h>
#include <cuda_fp16.h>
#include <math.h>

// Problem constants (fixed by the dataset generator)
#define NATOMS 8192
#define NEDGE  262144
#define KNB    32
#define HD     128
#define NFH    128
#define NGAUSS 50
#define NLAY   6
#define NGRAPH 32
#define NPERG  256
#define CUTR   10.0f
#define LOG2F_ 0.69314718055994530942f
#define PI_F   3.14159265358979323846f

// filter lookup table
#define MTAB   2048
#define DMAXT  8.661f
#define DELTA  (DMAXT / (float)(MTAB - 1))

typedef unsigned long long u64;

// packed f32x2 fma
#define FMA2(d, a, b, c) \
    asm("fma.rn.f32x2 %0, %1, %2, %3;" : "=l"(d) : "l"(a), "l"(b), "l"(c))
#define PACK2(d, x) \
    do { unsigned _u = __float_as_uint(x); \
         asm("mov.b64 %0, {%1, %1};" : "=l"(d) : "r"(_u)); } while (0)
#define UNPACK2(lo, hi, p) \
    do { unsigned _a, _b; \
         asm("mov.b64 {%0, %1}, %2;" : "=r"(_a), "=r"(_b) : "l"(p)); \
         lo = __uint_as_float(_a); hi = __uint_as_float(_b); } while (0)

// ---------------- device scratch ----------------
__device__ __half g_WtabH[NLAY * MTAB * HD];  // fp16 filter tables, 3.1 MB
__device__ int    g_ki[NEDGE];
__device__ float  g_al[NEDGE];
__device__ float  g_h[NATOMS * HD];
__device__ __half g_Xh[NATOMS * NFH];         // fp16 X (gather's only input)
__device__ float  g_agg[NATOMS * NFH];
__device__ float  g_S;

__device__ __forceinline__ float sspf(float x) {
    float e = __expf(-fabsf(x));
    return fmaxf(x, 0.0f) + __logf(1.0f + e) - LOG2F_;
}

__device__ __forceinline__ uint4 pack8h(const float* a) {
    __half2 h0 = __floats2half2_rn(a[0], a[1]);
    __half2 h1 = __floats2half2_rn(a[2], a[3]);
    __half2 h2 = __floats2half2_rn(a[4], a[5]);
    __half2 h3 = __floats2half2_rn(a[6], a[7]);
    uint4 pk;
    pk.x = *(unsigned*)&h0; pk.y = *(unsigned*)&h1;
    pk.z = *(unsigned*)&h2; pk.w = *(unsigned*)&h3;
    return pk;
}

// ---------------- edge precompute + output zero (fused) ----------------
__global__ void __launch_bounds__(256) edge_pre_kernel(const float* __restrict__ pos,
                                                       const int* __restrict__ ei,
                                                       float* __restrict__ out, int out_n) {
    int gid = blockIdx.x * blockDim.x + threadIdx.x;
    for (int e = gid; e < NEDGE; e += gridDim.x * blockDim.x) {
        int s = ei[e], t = ei[NEDGE + e];
        float dx = pos[3 * s + 0] - pos[3 * t + 0];
        float dy = pos[3 * s + 1] - pos[3 * t + 1];
        float dz = pos[3 * s + 2] - pos[3 * t + 2];
        float d = sqrtf(dx * dx + dy * dy + dz * dz);
        float tt = d * ((float)(MTAB - 1) / DMAXT);
        int k = (int)tt;
        if (k > MTAB - 2) k = MTAB - 2;
        g_ki[e] = k;
        g_al[e] = tt - (float)k;
    }
    for (int i = gid; i < out_n; i += gridDim.x * blockDim.x)
        out[i] = 0.0f;
}

// ---------------- filter table build (proven stage-A/B SIMT core, fp16 out) ----------
__global__ void __launch_bounds__(256, 1) table_kernel(
    const float* __restrict__ w1a, const float* __restrict__ b1a,
    const float* __restrict__ w2a, const float* __restrict__ b2a)
{
    extern __shared__ float sm[];
    float* s_w1 = sm;                        // [50][128]
    float* s_b1 = s_w1 + NGAUSS * NFH;
    float* s_b2 = s_b1 + NFH;
    float* s_w2 = s_b2 + NFH;                // [128][128]
    float* s_ea = s_w2 + NFH * NFH;          // [50][128]
    float* s_tT = s_ea + NGAUSS * 128;       // [128][128] swizzled

    const int l  = blockIdx.x >> 4;          // MTAB/128 = 16 blocks per layer
    const int m0 = (blockIdx.x & 15) * 128;
    const float* w1 = w1a + l * NGAUSS * NFH;
    const float* b1 = b1a + l * NFH;
    const float* w2 = w2a + l * NFH * NFH;
    const float* b2 = b2a + l * NFH;

    const int tid = threadIdx.x;
    for (int i = tid; i < NGAUSS * NFH; i += 256) s_w1[i] = w1[i];
    for (int i = tid; i < NFH * NFH;   i += 256) s_w2[i] = w2[i];
    if (tid < NFH) { s_b1[tid] = b1[tid]; s_b2[tid] = b2[tid]; }

    const float step  = CUTR / (float)(NGAUSS - 1);
    const float coeff = -0.5f / (step * step);
    for (int i = tid; i < NGAUSS * 128; i += 256) {
        int j = i >> 7, r = i & 127;
        float d = (float)(m0 + r) * DELTA;
        float u = d - (float)j * step;
        s_ea[j * 128 + r] = __expf(coeff * u * u);
    }
    __syncthreads();

    const int f8 = tid & 15, eg = tid >> 4;
    const int f0 = f8 * 8,   e0 = eg * 8;
    const int xf = (f8 & 7) << 2;

    u64 acc2[8][4];
    {
        const ulonglong2* bp = (const ulonglong2*)&s_b1[f0];
        ulonglong2 bA = bp[0], bB = bp[1];
#pragma unroll
        for (int ee = 0; ee < 8; ee++) {
            acc2[ee][0] = bA.x; acc2[ee][1] = bA.y;
            acc2[ee][2] = bB.x; acc2[ee][3] = bB.y;
        }
    }
    for (int j = 0; j < NGAUSS; j++) {
        const ulonglong2* wp = (const ulonglong2*)&s_w1[j * NFH + f0];
        ulonglong2 wA = wp[0], wB = wp[1];
        float4 ea0 = *(const float4*)&s_ea[j * 128 + e0];
        float4 ea1 = *(const float4*)&s_ea[j * 128 + e0 + 4];
        float ev[8] = {ea0.x, ea0.y, ea0.z, ea0.w, ea1.x, ea1.y, ea1.z, ea1.w};
#pragma unroll
        for (int ee = 0; ee < 8; ee++) {
            u64 evp; PACK2(evp, ev[ee]);
            FMA2(acc2[ee][0], evp, wA.x, acc2[ee][0]);
            FMA2(acc2[ee][1], evp, wA.y, acc2[ee][1]);
            FMA2(acc2[ee][2], evp, wB.x, acc2[ee][2]);
            FMA2(acc2[ee][3], evp, wB.y, acc2[ee][3]);
        }
    }
    {
        float a[8][8];
#pragma unroll
        for (int ee = 0; ee < 8; ee++)
#pragma unroll
            for (int fp = 0; fp < 4; fp++)
                UNPACK2(a[ee][2 * fp], a[ee][2 * fp + 1], acc2[ee][fp]);
#pragma unroll
        for (int ff = 0; ff < 8; ff++) {
            float4 v0 = make_float4(sspf(a[0][ff]), sspf(a[1][ff]),
                                    sspf(a[2][ff]), sspf(a[3][ff]));
            float4 v1 = make_float4(sspf(a[4][ff]), sspf(a[5][ff]),
                                    sspf(a[6][ff]), sspf(a[7][ff]));
            *(float4*)&s_tT[(f0 + ff) * NFH + (e0 ^ xf)]       = v0;
            *(float4*)&s_tT[(f0 + ff) * NFH + ((e0 + 4) ^ xf)] = v1;
        }
    }
    __syncthreads();

    {
        const ulonglong2* bp = (const ulonglong2*)&s_b2[f0];
        ulonglong2 bA = bp[0], bB = bp[1];
#pragma unroll
        for (int ee = 0; ee < 8; ee++) {
            acc2[ee][0] = bA.x; acc2[ee][1] = bA.y;
            acc2[ee][2] = bB.x; acc2[ee][3] = bB.y;
        }
    }
    for (int j = 0; j < NFH; j++) {
        const ulonglong2* wp = (const ulonglong2*)&s_w2[j * NFH + f0];
        ulonglong2 wA = wp[0], wB = wp[1];
        const int xj = ((j >> 3) & 7) << 2;
        float4 t0 = *(const float4*)&s_tT[j * NFH + (e0 ^ xj)];
        float4 t1 = *(const float4*)&s_tT[j * NFH + ((e0 + 4) ^ xj)];
        float tv[8] = {t0.x, t0.y, t0.z, t0.w, t1.x, t1.y, t1.z, t1.w};
#pragma unroll
        for (int ee = 0; ee < 8; ee++) {
            u64 tp; PACK2(tp, tv[ee]);
            FMA2(acc2[ee][0], tp, wA.x, acc2[ee][0]);
            FMA2(acc2[ee][1], tp, wA.y, acc2[ee][1]);
            FMA2(acc2[ee][2], tp, wB.x, acc2[ee][2]);
            FMA2(acc2[ee][3], tp, wB.y, acc2[ee][3]);
        }
    }

#pragma unroll
    for (int ee = 0; ee < 8; ee++) {
        float a[8];
#pragma unroll
        for (int fp = 0; fp < 4; fp++) UNPACK2(a[2 * fp], a[2 * fp + 1], acc2[ee][fp]);
        int m = m0 + e0 + ee;
        float d = (float)m * DELTA;
        float Cr = 0.5f * (cosf(d * (PI_F / CUTR)) + 1.0f);
        float b[8];
#pragma unroll
        for (int q = 0; q < 8; q++) b[q] = a[q] * Cr;
        *(uint4*)&g_WtabH[((size_t)l * MTAB + m) * HD + f0] = pack8h(b);
    }
}

// ---------------- gather: warp per atom, metadata via shfl, fp16 table + fp16 X ----
// (round-14 proven version: fp32 lerp/product, half2 unpacks)
__global__ void __launch_bounds__(256) gather_kernel(const int* __restrict__ ei, int layer)
{
    const int warp = threadIdx.x >> 5, lane = threadIdx.x & 31;
    const int atom = blockIdx.x * 8 + warp;
    const int eb = atom * KNB;
    const int c4 = lane * 4;
    const __half* tab = &g_WtabH[(size_t)layer * MTAB * HD];

    int   ki_r  = g_ki[eb + lane];
    float al_r  = g_al[eb + lane];
    int   src_r = ei[eb + lane];

    float4 acc = make_float4(0.0f, 0.0f, 0.0f, 0.0f);
#pragma unroll 4
    for (int e = 0; e < KNB; e++) {
        int   k  = __shfl_sync(0xffffffffu, ki_r,  e);
        float al = __shfl_sync(0xffffffffu, al_r,  e);
        int   s  = __shfl_sync(0xffffffffu, src_r, e);
        uint2 u0 = *(const uint2*)&tab[(size_t)k * HD + c4];
        uint2 u1 = *(const uint2*)&tab[(size_t)(k + 1) * HD + c4];
        uint2 ux = *(const uint2*)&g_Xh[s * HD + c4];
        float2 a0 = __half22float2(*(__half2*)&u0.x);
        float2 a1 = __half22float2(*(__half2*)&u0.y);
        float2 b0 = __half22float2(*(__half2*)&u1.x);
        float2 b1 = __half22float2(*(__half2*)&u1.y);
        float2 x0 = __half22float2(*(__half2*)&ux.x);
        float2 x1 = __half22float2(*(__half2*)&ux.y);
        float w0 = fmaf(al, b0.x - a0.x, a0.x);
        float w1 = fmaf(al, b0.y - a0.y, a0.y);
        float w2 = fmaf(al, b1.x - a1.x, a1.x);
        float w3 = fmaf(al, b1.y - a1.y, a1.y);
        acc.x = fmaf(x0.x, w0, acc.x);
        acc.y = fmaf(x0.y, w1, acc.y);
        acc.z = fmaf(x1.x, w2, acc.z);
        acc.w = fmaf(x1.y, w3, acc.w);
    }
    *(float4*)&g_agg[atom * HD + c4] = acc;
}

// ---------------- node GEMM: Xh = (emb[z]) @ cf1 (fp16 out), materialize g_h ----------
__global__ void __launch_bounds__(256, 1) gemm0_kernel(
    const float* __restrict__ W, const int* __restrict__ z, const float* __restrict__ emb)
{
    extern __shared__ float smem_dyn[];
    float* s_w = smem_dyn;
    float* s_x = s_w + NFH * NFH;

    const int tid = threadIdx.x;
    for (int i = tid; i < NFH * NFH; i += 256) s_w[i] = W[i];
    __syncthreads();

    const int f8 = tid & 15, aq = tid >> 4;
    const int f0 = f8 * 8,   a0 = aq * 4;

    for (int blk = blockIdx.x; blk < NATOMS / 64; blk += gridDim.x) {
        int abase = blk * 64;
        for (int i = tid; i < 64 * NFH; i += 256) {
            int a = i >> 7, f = i & 127;
            float v = emb[z[abase + a] * HD + f];
            s_x[i] = v;
            g_h[abase * NFH + i] = v;
        }
        __syncthreads();

        u64 acc2[4][4];
#pragma unroll
        for (int aa = 0; aa < 4; aa++)
#pragma unroll
            for (int k = 0; k < 4; k++) acc2[aa][k] = 0ull;
        for (int j = 0; j < NFH; j++) {
            const ulonglong2* wp = (const ulonglong2*)&s_w[j * NFH + f0];
            ulonglong2 wA = wp[0], wB = wp[1];
#pragma unroll
            for (int aa = 0; aa < 4; aa++) {
                float xv = s_x[(a0 + aa) * NFH + j];
                u64 xp; PACK2(xp, xv);
                FMA2(acc2[aa][0], xp, wA.x, acc2[aa][0]);
                FMA2(acc2[aa][1], xp, wA.y, acc2[aa][1]);
                FMA2(acc2[aa][2], xp, wB.x, acc2[aa][2]);
                FMA2(acc2[aa][3], xp, wB.y, acc2[aa][3]);
            }
        }
#pragma unroll
        for (int aa = 0; aa < 4; aa++) {
            float a[8];
#pragma unroll
            for (int fp = 0; fp < 4; fp++) UNPACK2(a[2 * fp], a[2 * fp + 1], acc2[aa][fp]);
            *(uint4*)&g_Xh[(abase + a0 + aa) * NFH + f0] = pack8h(a);
        }
        __syncthreads();
    }
}

// ---- fused node chain (64-atom tiles): P=ssp(agg@cf2+b2); h+=P@intw+bi; Xh=h@cf1n ----
template <int HAS_NEXT>
__global__ void __launch_bounds__(256, 1) node_fused_kernel(
    const float* __restrict__ cf2w, const float* __restrict__ cf2b,
    const float* __restrict__ intw, const float* __restrict__ intb,
    const float* __restrict__ cf1n)
{
    extern __shared__ float sm[];
    float* s_w2 = sm;                                  // [128][128]
    float* s_wi = s_w2 + NFH * NFH;                    // [128][128]
    float* s_wn = s_wi + NFH * NFH;                    // [128][128] if HAS_NEXT
    float* s_x  = s_wn + (HAS_NEXT ? NFH * NFH : 0);   // [64][128]
    float* s_b2 = s_x + 64 * NFH;                      // [128]
    float* s_bi = s_b2 + NFH;                          // [128]

    const int tid = threadIdx.x;
    for (int i = tid; i < NFH * NFH; i += 256) s_w2[i] = cf2w[i];
    for (int i = tid; i < NFH * NFH; i += 256) s_wi[i] = intw[i];
    if (HAS_NEXT)
        for (int i = tid; i < NFH * NFH; i += 256) s_wn[i] = cf1n[i];
    if (tid < NFH) { s_b2[tid] = cf2b[tid]; s_bi[tid] = intb[tid]; }

    const int f8 = tid & 15, aq = tid >> 4;
    const int f0 = f8 * 8,   a0 = aq * 4;
    const int abase = blockIdx.x * 64;                 // grid = 128

    for (int i = tid; i < 64 * NFH; i += 256)
        s_x[i] = g_agg[abase * NFH + i];
    __syncthreads();

    u64 acc2[4][4];
    // ---- GEMM1: P = ssp(agg @ cf2 + b2) ----
    {
        const ulonglong2* bp = (const ulonglong2*)&s_b2[f0];
        ulonglong2 bA = bp[0], bB = bp[1];
#pragma unroll
        for (int aa = 0; aa < 4; aa++) {
            acc2[aa][0] = bA.x; acc2[aa][1] = bA.y;
            acc2[aa][2] = bB.x; acc2[aa][3] = bB.y;
        }
    }
    for (int j = 0; j < NFH; j++) {
        const ulonglong2* wp = (const ulonglong2*)&s_w2[j * NFH + f0];
        ulonglong2 wA = wp[0], wB = wp[1];
#pragma unroll
        for (int aa = 0; aa < 4; aa++) {
            float xv = s_x[(a0 + aa) * NFH + j];
            u64 xp; PACK2(xp, xv);
            FMA2(acc2[aa][0], xp, wA.x, acc2[aa][0]);
            FMA2(acc2[aa][1], xp, wA.y, acc2[aa][1]);
            FMA2(acc2[aa][2], xp, wB.x, acc2[aa][2]);
            FMA2(acc2[aa][3], xp, wB.y, acc2[aa][3]);
        }
    }
    float P[4][8];
#pragma unroll
    for (int aa = 0; aa < 4; aa++) {
        float a[8];
#pragma unroll
        for (int fp = 0; fp < 4; fp++) UNPACK2(a[2 * fp], a[2 * fp + 1], acc2[aa][fp]);
#pragma unroll
        for (int q = 0; q < 8; q++) P[aa][q] = sspf(a[q]);
    }
    __syncthreads();
#pragma unroll
    for (int aa = 0; aa < 4; aa++) {
        *(float4*)&s_x[(a0 + aa) * NFH + f0]     = make_float4(P[aa][0], P[aa][1], P[aa][2], P[aa][3]);
        *(float4*)&s_x[(a0 + aa) * NFH + f0 + 4] = make_float4(P[aa][4], P[aa][5], P[aa][6], P[aa][7]);
    }
    __syncthreads();

    // ---- GEMM2: hnew = h + P @ intw + bi ----
    {
        const ulonglong2* bp = (const ulonglong2*)&s_bi[f0];
        ulonglong2 bA = bp[0], bB = bp[1];
#pragma unroll
        for (int aa = 0; aa < 4; aa++) {
            acc2[aa][0] = bA.x; acc2[aa][1] = bA.y;
            acc2[aa][2] = bB.x; acc2[aa][3] = bB.y;
        }
    }
    for (int j = 0; j < NFH; j++) {
        const ulonglong2* wp = (const ulonglong2*)&s_wi[j * NFH + f0];
        ulonglong2 wA = wp[0], wB = wp[1];
#pragma unroll
        for (int aa = 0; aa < 4; aa++) {
            float xv = s_x[(a0 + aa) * NFH + j];
            u64 xp; PACK2(xp, xv);
            FMA2(acc2[aa][0], xp, wA.x, acc2[aa][0]);
            FMA2(acc2[aa][1], xp, wA.y, acc2[aa][1]);
            FMA2(acc2[aa][2], xp, wB.x, acc2[aa][2]);
            FMA2(acc2[aa][3], xp, wB.y, acc2[aa][3]);
        }
    }
    float hnew[4][8];
#pragma unroll
    for (int aa = 0; aa < 4; aa++) {
        float a[8];
#pragma unroll
        for (int fp = 0; fp < 4; fp++) UNPACK2(a[2 * fp], a[2 * fp + 1], acc2[aa][fp]);
        int row = (abase + a0 + aa) * NFH + f0;
        float4 y0 = *(const float4*)&g_h[row];
        float4 y1 = *(const float4*)&g_h[row + 4];
        hnew[aa][0] = y0.x + a[0]; hnew[aa][1] = y0.y + a[1];
        hnew[aa][2] = y0.z + a[2]; hnew[aa][3] = y0.w + a[3];
        hnew[aa][4] = y1.x + a[4]; hnew[aa][5] = y1.y + a[5];
        hnew[aa][6] = y1.z + a[6]; hnew[aa][7] = y1.w + a[7];
        *(float4*)&g_h[row]     = make_float4(hnew[aa][0], hnew[aa][1], hnew[aa][2], hnew[aa][3]);
        *(float4*)&g_h[row + 4] = make_float4(hnew[aa][4], hnew[aa][5], hnew[aa][6], hnew[aa][7]);
    }

    if (HAS_NEXT) {
        __syncthreads();
#pragma unroll
        for (int aa = 0; aa < 4; aa++) {
            *(float4*)&s_x[(a0 + aa) * NFH + f0]     =
                make_float4(hnew[aa][0], hnew[aa][1], hnew[aa][2], hnew[aa][3]);
            *(float4*)&s_x[(a0 + aa) * NFH + f0 + 4] =
                make_float4(hnew[aa][4], hnew[aa][5], hnew[aa][6], hnew[aa][7]);
        }
        __syncthreads();

        // ---- GEMM3: Xh = hnew @ cf1next (fp16 out) ----
#pragma unroll
        for (int aa = 0; aa < 4; aa++)
#pragma unroll
            for (int k = 0; k < 4; k++) acc2[aa][k] = 0ull;
        for (int j = 0; j < NFH; j++) {
            const ulonglong2* wp = (const ulonglong2*)&s_wn[j * NFH + f0];
            ulonglong2 wA = wp[0], wB = wp[1];
#pragma unroll
            for (int aa = 0; aa < 4; aa++) {
                float xv = s_x[(a0 + aa) * NFH + j];
                u64 xp; PACK2(xp, xv);
                FMA2(acc2[aa][0], xp, wA.x, acc2[aa][0]);
                FMA2(acc2[aa][1], xp, wA.y, acc2[aa][1]);
                FMA2(acc2[aa][2], xp, wB.x, acc2[aa][2]);
                FMA2(acc2[aa][3], xp, wB.y, acc2[aa][3]);
            }
        }
#pragma unroll
        for (int aa = 0; aa < 4; aa++) {
            float a[8];
#pragma unroll
            for (int fp = 0; fp < 4; fp++) UNPACK2(a[2 * fp], a[2 * fp + 1], acc2[aa][fp]);
            *(uint4*)&g_Xh[(abase + a0 + aa) * NFH + f0] = pack8h(a);
        }
    }
}

// ---------------- FiLM bias, algebraically collapsed, float4 loads ----------------
__global__ void __launch_bounds__(256) bias_kernel(
    const int* __restrict__ dom_ids, const float* __restrict__ dom_emb,
    const float* __restrict__ fw1, const float* __restrict__ fb1,
    const float* __restrict__ fw2, const float* __restrict__ fb2,
    const float* __restrict__ bw,  const float* __restrict__ bb)
{
    __shared__ float s_v[128];
    __shared__ float s_u[128];
    __shared__ float s_de[NGRAPH * 64];
    __shared__ float s_red[8];
    int tid = threadIdx.x;

    if (tid < 128) {
        float s = 0.0f;
        const float4* r = (const float4*)&bw[tid * 128];
#pragma unroll 8
        for (int h = 0; h < 32; h++) { float4 v = r[h]; s += v.x + v.y + v.z + v.w; }
        s_v[tid] = s;
    }
    for (int i = tid; i < NGRAPH * 64; i += 256) {
        int g = i >> 6, k = i & 63;
        s_de[i] = dom_emb[dom_ids[g] * 64 + k];
    }
    __syncthreads();
    if (tid < 128) {
        float s = 0.0f;
        const float4* r = (const float4*)&fw2[tid * 128];
        const float4* v4 = (const float4*)s_v;
#pragma unroll 8
        for (int k = 0; k < 32; k++) {
            float4 w = r[k], v = v4[k];
            s += w.x * v.x + w.y * v.y + w.z * v.z + w.w * v.w;
        }
        s_u[tid] = s;
    }
    __syncthreads();

    float sl = 0.0f;
    if (tid < 128) sl += (float)NGRAPH * (fb2[tid] * s_v[tid] + bb[tid]);
    for (int idx = tid; idx < NGRAPH * 128; idx += 256) {
        int g = idx >> 7, j = idx & 127;
        float a = fb1[j];
#pragma unroll 4
        for (int i = 0; i < 64; i++) a += s_de[g * 64 + i] * fw1[i * 128 + j];
        sl += fmaxf(a, 0.0f) * s_u[j];
    }
    for (int o = 16; o; o >>= 1) sl += __shfl_xor_sync(0xffffffffu, sl, o);
    if ((tid & 31) == 0) s_red[tid >> 5] = sl;
    __syncthreads();
    if (tid == 0) {
        float v = 0.0f;
        for (int w = 0; w < 8; w++) v += s_red[w];
        g_S = v;
    }
}

// ---------------- output head ----------------
__global__ void __launch_bounds__(256) energy_kernel(
    const float* __restrict__ w1, const float* __restrict__ b1,
    const float* __restrict__ w2, const float* __restrict__ b2,
    float* __restrict__ out)
{
    __shared__ float s_w1[HD * 64];
    __shared__ float s_w2[64];
    __shared__ float s_red[8];
    int tid = threadIdx.x;
    for (int i = tid; i < HD * 64; i += 256) s_w1[i] = w1[i];
    if (tid < 64) s_w2[tid] = w2[tid];
    __syncthreads();

    int atom = blockIdx.x * NPERG + tid;
    float e = b2[0];
#pragma unroll
    for (int half = 0; half < 2; half++) {
        float u[32];
#pragma unroll
        for (int f = 0; f < 32; f++) u[f] = b1[half * 32 + f];
        for (int j = 0; j < HD; j++) {
            float hv = g_h[atom * HD + j];
#pragma unroll
            for (int f = 0; f < 32; f++) u[f] += hv * s_w1[j * 64 + half * 32 + f];
        }
#pragma unroll
        for (int f = 0; f < 32; f++) e += sspf(u[f]) * s_w2[half * 32 + f];
    }

    for (int o = 16; o; o >>= 1) e += __shfl_xor_sync(0xffffffffu, e, o);
    if ((tid & 31) == 0) s_red[tid >> 5] = e;
    __syncthreads();
    if (tid == 0) {
        float tot = 0.0f;
        for (int w = 0; w < 8; w++) tot += s_red[w];
        out[blockIdx.x] = (float)NGRAPH * tot + g_S;
    }
}

// ---------------- launch ----------------
extern "C" void kernel_launch(void* const* d_in, const int* in_sizes, int n_in,
                              void* d_out, int out_size)
{
    const float* pos    = (const float*)d_in[0];
    const int*   z      = (const int*)  d_in[1];
    const int*   ei     = (const int*)  d_in[3];
    const int*   dom    = (const int*)  d_in[4];
    const float* emb    = (const float*)d_in[5];
    const float* mlp_w1 = (const float*)d_in[6];
    const float* mlp_b1 = (const float*)d_in[7];
    const float* mlp_w2 = (const float*)d_in[8];
    const float* mlp_b2 = (const float*)d_in[9];
    const float* cf1    = (const float*)d_in[10];
    const float* cf2    = (const float*)d_in[11];
    const float* cf2b   = (const float*)d_in[12];
    const float* intw   = (const float*)d_in[13];
    const float* intb   = (const float*)d_in[14];
    const float* ow1    = (const float*)d_in[15];
    const float* ob1    = (const float*)d_in[16];
    const float* ow2    = (const float*)d_in[17];
    const float* ob2    = (const float*)d_in[18];
    const float* dome   = (const float*)d_in[19];
    const float* fw1    = (const float*)d_in[20];
    const float* fb1    = (const float*)d_in[21];
    const float* fw2    = (const float*)d_in[22];
    const float* fb2    = (const float*)d_in[23];
    const float* bw     = (const float*)d_in[26];
    const float* bb     = (const float*)d_in[27];
    float* out = (float*)d_out;

    const int TAB_SMEM  = (NGAUSS * NFH + NFH + NFH + NFH * NFH +
                           NGAUSS * 128 + 128 * NFH) * (int)sizeof(float);
    const int GEMM0_SMEM = (NFH * NFH + 64 * NFH) * (int)sizeof(float);
    const int NF1_SMEM  = (3 * NFH * NFH + 64 * NFH + 2 * NFH) * (int)sizeof(float);
    const int NF0_SMEM  = (2 * NFH * NFH + 64 * NFH + 2 * NFH) * (int)sizeof(float);

    cudaFuncSetAttribute(table_kernel,  cudaFuncAttributeMaxDynamicSharedMemorySize, TAB_SMEM);
    cudaFuncSetAttribute(gemm0_kernel,  cudaFuncAttributeMaxDynamicSharedMemorySize, GEMM0_SMEM);
    cudaFuncSetAttribute(node_fused_kernel<1>, cudaFuncAttributeMaxDynamicSharedMemorySize, NF1_SMEM);
    cudaFuncSetAttribute(node_fused_kernel<0>, cudaFuncAttributeMaxDynamicSharedMemorySize, NF0_SMEM);

    edge_pre_kernel<<<1024, 256>>>(pos, ei, out, out_size);
    table_kernel<<<NLAY * (MTAB / 128), 256, TAB_SMEM>>>(mlp_w1, mlp_b1, mlp_w2, mlp_b2);
    gemm0_kernel<<<128, 256, GEMM0_SMEM>>>(cf1, z, emb);
    gather_kernel<<<NATOMS / 8, 256>>>(ei, 0);      // layer 0 (ncu-captured slot)

    bias_kernel<<<1, 256>>>(dom, dome, fw1, fb1, fw2, fb2, bw, bb);

    node_fused_kernel<1><<<NATOMS / 64, 256, NF1_SMEM>>>(cf2, cf2b, intw, intb,
                                                         cf1 + 1 * HD * NFH);

    for (int l = 1; l < NLAY; l++) {
        gather_kernel<<<NATOMS / 8, 256>>>(ei, l);
        if (l + 1 < NLAY)
            node_fused_kernel<1><<<NATOMS / 64, 256, NF1_SMEM>>>(
                cf2 + l * NFH * HD, cf2b + l * HD,
                intw + l * HD * HD, intb + l * HD,
                cf1 + (l + 1) * HD * NFH);
        else
            node_fused_kernel<0><<<NATOMS / 64, 256, NF0_SMEM>>>(
                cf2 + l * NFH * HD, cf2b + l * HD,
                intw + l * HD * HD, intb + l * HD,
                nullptr);
    }

    energy_kernel<<<NGRAPH, 256>>>(ow1, ob1, ow2, ob2, out);
}